// round 8
// baseline (speedup 1.0000x reference)
#include <cuda_runtime.h>
#include <cuda_fp16.h>
#include <math.h>

// ---------------------------------------------------------------------------
// Fused 3-layer GCN, fixed 21-node hand skeleton, 50000 graphs.
// R8: crew-split + software pipeline.
//   CTA = 2 independent crews x 4 warps. Crew tile = 4 graphs (84+4pad rows).
//   Double-buffered H -> 2 crew-scoped named barriers per tile, P1(t+1)
//   overlapped with the MMA interval. XOR-swizzled 128B rows for A and H
//   (no padding), W3 read from global (L1-resident), 1/21 folded into pool
//   weights. 3 CTAs/SM.
// ---------------------------------------------------------------------------

#define NODES   21
#define NCLS    29
#define NT4     12500         // 50000 / 4
#define GRID    444           // 148 SM x 3 CTA
#define NSTREAM 888           // 444 CTAs x 2 crews
#define R2C     0.70710678118654752440f
#define WROOT   4.535533905932737f

// ---- smem byte offsets ----------------------------------------------------
#define SB_H    0             // 4 bufs (2 crews x 2) x 88 rows x 128B = 45056
#define HBUF    11264
#define SB_A    45056         // W2'*s2 fp16 swizzled [128 j][128B]    16384
#define SB_PV   61440         // 2 crews x 128 j x 4 g f32             4096
#define SB_PY   65536         // 2 crews x 4 w x 4 g x 32 f32          4096
#define SB_T2   69632         // 128 f32
#define SB_B3   70144         // 32 f32
#define SB_C    70272         // W1 [3][64] f32                        768
#define SB_S1   71040         // 64 f32
#define SB_T1   71296         // 64 f32
#define SB_TOT  71552         // x3 CTA = 214,656

// ---- PTX helpers ----------------------------------------------------------
__device__ __forceinline__ unsigned smem_u32(const void* p) {
    unsigned a;
    asm("{ .reg .u64 t; cvta.to.shared.u64 t, %1; cvt.u32.u64 %0, t; }"
        : "=r"(a) : "l"(p));
    return a;
}
__device__ __forceinline__ void ldsm4(unsigned& r0, unsigned& r1,
                                      unsigned& r2, unsigned& r3, unsigned a) {
    asm volatile("ldmatrix.sync.aligned.m8n8.x4.shared.b16 {%0,%1,%2,%3}, [%4];"
                 : "=r"(r0), "=r"(r1), "=r"(r2), "=r"(r3) : "r"(a));
}
__device__ __forceinline__ void ldsm2(unsigned& r0, unsigned& r1, unsigned a) {
    asm volatile("ldmatrix.sync.aligned.m8n8.x2.shared.b16 {%0,%1}, [%2];"
                 : "=r"(r0), "=r"(r1) : "r"(a));
}
__device__ __forceinline__ void mma16816(float* c, const unsigned* a,
                                         unsigned b0, unsigned b1) {
    asm volatile(
        "mma.sync.aligned.m16n8k16.row.col.f32.f16.f16.f32 "
        "{%0,%1,%2,%3}, {%4,%5,%6,%7}, {%8,%9}, {%0,%1,%2,%3};"
        : "+f"(c[0]), "+f"(c[1]), "+f"(c[2]), "+f"(c[3])
        : "r"(a[0]), "r"(a[1]), "r"(a[2]), "r"(a[3]), "r"(b0), "r"(b1));
}
__device__ __forceinline__ void barc(int id) {   // crew barrier: 128 threads
    asm volatile("bar.sync %0, 128;" :: "r"(id) : "memory");
}
__device__ __forceinline__ float wselS(int l) {  // pool weight * (1/21)
    return (l == 0) ? (WROOT / 21.f)
         : (((l & 3) == 0) ? (0.5f / 21.f) : (1.0f / 21.f));
}
__device__ __forceinline__ float pick4(const float* v, int s) {
    return (s == 0) ? v[0] : (s == 1) ? v[1] : (s == 2) ? v[2] : v[3];
}
__device__ __forceinline__ int imin(int a, int b) { return a < b ? a : b; }

// ---- phase 1: layer1 + mix + BN + ReLU + mix2 -> H buffer (swizzled) ------
__device__ __forceinline__ void phase1(char* smc, int hoff, const float* xg,
                                       int wl, int lane) {
    const float* smf = (const float*)smc;
    const float2 w1a = ((const float2*)(smf + SB_C / 4))[lane];
    const float2 w1b = ((const float2*)(smf + SB_C / 4 + 64))[lane];
    const float2 w1c = ((const float2*)(smf + SB_C / 4 + 128))[lane];
    const float2 s1  = ((const float2*)(smf + SB_S1 / 4))[lane];
    const float2 t1  = ((const float2*)(smf + SB_T1 / 4))[lane];
    const float xv0 = xg[lane];
    const float xv1 = (lane < 31) ? xg[32 + lane] : 0.f;
    const int rb  = 21 * wl;
    const int c4  = lane >> 2;
    const int lo  = (lane & 3) * 4;

    float2 z0, h0;
    {
        float xa = __shfl_sync(0xffffffffu, xv0, 0);
        float xb = __shfl_sync(0xffffffffu, xv0, 1);
        float xc = __shfl_sync(0xffffffffu, xv0, 2);
        z0.x = fmaf(xa, w1a.x, fmaf(xb, w1b.x, xc * w1c.x));
        z0.y = fmaf(xa, w1a.y, fmaf(xb, w1b.y, xc * w1c.y));
        h0.x = fmaxf(fmaf(z0.x, s1.x, t1.x), 0.f);
        h0.y = fmaxf(fmaf(z0.y, s1.y, t1.y), 0.f);
        int sw = ((c4 ^ (rb & 7)) << 4);
        *(__half2*)(smc + hoff + rb * 128 + sw + lo) =
            __floats2half2_rn(h0.x, h0.y);
    }
    #pragma unroll
    for (int f = 0; f < 5; ++f) {
        float2 zp = z0, hp = h0;
        #pragma unroll
        for (int i = 0; i < 4; ++i) {
            const int n = 1 + 4 * f + i;
            const float cp = (i == 0) ? R2C : 0.5f;
            const int i0 = 3 * n;
            float xa = (i0 < 32) ? __shfl_sync(0xffffffffu, xv0, i0)
                                 : __shfl_sync(0xffffffffu, xv1, i0 - 32);
            float xb = (i0 + 1 < 32) ? __shfl_sync(0xffffffffu, xv0, i0 + 1)
                                     : __shfl_sync(0xffffffffu, xv1, i0 - 31);
            float xc = (i0 + 2 < 32) ? __shfl_sync(0xffffffffu, xv0, i0 + 2)
                                     : __shfl_sync(0xffffffffu, xv1, i0 - 30);
            float2 zn, hn;
            zn.x = fmaf(xa, w1a.x, fmaf(xb, w1b.x, xc * w1c.x));
            zn.y = fmaf(xa, w1a.y, fmaf(xb, w1b.y, xc * w1c.y));
            float m1x = fmaf(0.5f, zn.x, cp * zp.x);
            float m1y = fmaf(0.5f, zn.y, cp * zp.y);
            hn.x = fmaxf(fmaf(m1x, s1.x, t1.x), 0.f);
            hn.y = fmaxf(fmaf(m1y, s1.y, t1.y), 0.f);
            float m2x = fmaf(0.5f, hn.x, cp * hp.x);
            float m2y = fmaf(0.5f, hn.y, cp * hp.y);
            const int row = rb + n;
            int sw = ((c4 ^ (row & 7)) << 4);
            *(__half2*)(smc + hoff + row * 128 + sw + lo) =
                __floats2half2_rn(m2x, m2y);
            zp = zn; hp = hn;
        }
    }
}

// ---------------------------------------------------------------------------
__global__ void __launch_bounds__(256, 3)
gcn_crew_kernel(const float* __restrict__ x,
                const float* __restrict__ W1, const float* __restrict__ b1,
                const float* __restrict__ g1, const float* __restrict__ be1,
                const float* __restrict__ m1, const float* __restrict__ v1,
                const float* __restrict__ W2, const float* __restrict__ b2,
                const float* __restrict__ g2, const float* __restrict__ be2,
                const float* __restrict__ m2, const float* __restrict__ v2,
                const float* __restrict__ W3, const float* __restrict__ b3,
                float* __restrict__ out) {
    extern __shared__ char smc[];
    float* smf = (float*)smc;
    const unsigned sb = smem_u32(smc);
    const int tid  = threadIdx.x;
    const int lane = tid & 31;
    const int wid  = tid >> 5;
    const int crew = wid >> 2;          // 0,1
    const int wl   = wid & 3;           // local warp = j-strip / graph

    // ---------------- staging (once per CTA) -------------------------------
    for (int i = tid; i < 8192; i += 256) {          // A = W2^T*diag(s2), swz
        int j = i & 127, k = i >> 7;
        float s = g2[j] * rsqrtf(v2[j] + 1e-5f);
        int off = SB_A + j * 128 + (((k >> 3) ^ (j & 7)) << 4) + ((k * 2) & 15);
        *(__half*)(smc + off) = __float2half(W2[k * 128 + j] * s);
    }
    for (int i = tid; i < 512; i += 256) {           // zero H pad rows 84..87
        int b = i >> 7, rem = i & 127;
        *(float*)(smc + SB_H + b * HBUF + 84 * 128 + rem * 4) = 0.f;
    }
    if (tid < 128) {
        float s = g2[tid] * rsqrtf(v2[tid] + 1e-5f);
        smf[SB_T2 / 4 + tid] = (b2[tid] - m2[tid]) * s + be2[tid];
    }
    if (tid < NCLS) smf[SB_B3 / 4 + tid] = b3[tid];
    for (int i = tid; i < 192; i += 256) smf[SB_C / 4 + i] = W1[i];
    if (tid < 64) {
        float s = g1[tid] * rsqrtf(v1[tid] + 1e-5f);
        smf[SB_S1 / 4 + tid] = s;
        smf[SB_T1 / 4 + tid] = (b1[tid] - m1[tid]) * s + be1[tid];
    }
    __syncthreads();

    // ---- per-warp invariants ---------------------------------------------
    float t2r[4];
    #pragma unroll
    for (int r = 0; r < 4; ++r)
        t2r[r] = smf[SB_T2 / 4 + 32 * wl + (lane >> 2) + 8 * r];
    const int cp2 = 2 * (lane & 3);
    const int hcrew = SB_H + crew * (2 * HBUF);
    unsigned bOff[4];
    #pragma unroll
    for (int kk = 0; kk < 4; ++kk)
        bOff[kk] = (lane & 7) * 128
                 + (((2 * kk + ((lane >> 3) & 1)) ^ (lane & 7)) << 4);

    // A fragments: static across all tiles -> load ONCE (32 regs)
    unsigned ah[4][2][4];
    #pragma unroll
    for (int kk = 0; kk < 4; ++kk)
        #pragma unroll
        for (int mt = 0; mt < 2; ++mt) {
            int row = 32 * wl + 16 * mt + (lane & 15);
            ldsm4(ah[kk][mt][0], ah[kk][mt][1], ah[kk][mt][2], ah[kk][mt][3],
                  sb + SB_A + row * 128
                  + ((((lane >> 4) + 2 * kk) ^ (lane & 7)) << 4));
        }

    const int barid = crew + 1;
    int t = blockIdx.x * 2 + crew;
    int buf = 0;

    // prologue: fill H buffer 0
    phase1(smc, hcrew, x + (size_t)(t * 4 + wl) * 63, wl, lane);
    barc(barid);

    for (; t < NT4; t += NSTREAM) {
        const int hoff = hcrew + buf * HBUF;

        // ---- phase 2: MMA (M=32 strip, 11 nt) + fused pooling -------------
        {
            unsigned bB[4];
            #pragma unroll
            for (int kk = 0; kk < 4; ++kk) bB[kk] = sb + hoff + bOff[kk];

            float v[4][4];
            #pragma unroll
            for (int r = 0; r < 4; ++r)
                #pragma unroll
                for (int g = 0; g < 4; ++g) v[r][g] = 0.f;

            #pragma unroll
            for (int nt = 0; nt < 11; ++nt) {
                float acc[8] = {0.f,0.f,0.f,0.f,0.f,0.f,0.f,0.f};
                #pragma unroll
                for (int kk = 0; kk < 4; ++kk) {
                    unsigned b0, b1;
                    ldsm2(b0, b1, bB[kk] + nt * 1024);
                    mma16816(acc,     ah[kk][0], b0, b1);
                    mma16816(acc + 4, ah[kk][1], b0, b1);
                }
                const int n0c = 8 * nt;
                const int gl  = n0c / 21;
                const int gh  = imin((n0c + 7) / 21, 3);
                const int bnd = 21 * (gl + 1);
                const int n0 = n0c + cp2, n1 = n0 + 1;
                const int l0 = n0 - ((n0 < bnd) ? 21 * gl : bnd);
                const int l1 = n1 - ((n1 < bnd) ? 21 * gl : bnd);
                float w0 = wselS(l0), w1 = wselS(l1);
                if (nt == 10) {                  // cols 84..87 are pad
                    if (n0 >= 84) w0 = 0.f;
                    if (n1 >= 84) w1 = 0.f;
                }
                #pragma unroll
                for (int r = 0; r < 4; ++r) {
                    float q0 = fmaxf(acc[2 * r]     + t2r[r], 0.f) * w0;
                    float q1 = fmaxf(acc[2 * r + 1] + t2r[r], 0.f) * w1;
                    if (gl == gh) {
                        v[r][gl] += q0 + q1;
                    } else {
                        float qlo = ((n0 < bnd) ? q0 : 0.f)
                                  + ((n1 < bnd) ? q1 : 0.f);
                        v[r][gl] += qlo;
                        v[r][gh] += (q0 + q1) - qlo;
                    }
                }
            }
            #pragma unroll
            for (int r = 0; r < 4; ++r)
                #pragma unroll
                for (int g = 0; g < 4; ++g) {
                    v[r][g] += __shfl_xor_sync(0xffffffffu, v[r][g], 1);
                    v[r][g] += __shfl_xor_sync(0xffffffffu, v[r][g], 2);
                }
            const int gs = lane & 3;
            #pragma unroll
            for (int r = 0; r < 4; ++r) {
                const int j = 32 * wl + (lane >> 2) + 8 * r;
                smf[SB_PV / 4 + crew * 512 + j * 4 + gs] = pick4(v[r], gs);
            }
        }

        // ---- phase 1 of NEXT tile into the other buffer (no barrier) ------
        {
            int tn = t + NSTREAM;
            if (tn < NT4)
                phase1(smc, hcrew + (buf ^ 1) * HBUF,
                       x + (size_t)(tn * 4 + wl) * 63, wl, lane);
        }
        buf ^= 1;
        barc(barid);                                 // BAR_A: PV ready

        // ---- phase 4: layer 3 partial over j-strip (W3 from gmem/L1) ------
        {
            const float* pvb = smf + SB_PV / 4 + crew * 512 + wl * 128;
            float y0 = 0.f, y1 = 0.f, y2 = 0.f, y3 = 0.f;
            #pragma unroll
            for (int jj = 0; jj < 32; ++jj) {
                const int j = 32 * wl + jj;
                float wc = (lane < NCLS) ? __ldg(W3 + j * NCLS + lane) : 0.f;
                float4 pv = *(const float4*)(pvb + jj * 4);
                y0 = fmaf(pv.x, wc, y0);
                y1 = fmaf(pv.y, wc, y1);
                y2 = fmaf(pv.z, wc, y2);
                y3 = fmaf(pv.w, wc, y3);
            }
            float* py = smf + SB_PY / 4 + crew * 512 + wl * 128;
            py[0 * 32 + lane] = y0;
            py[1 * 32 + lane] = y1;
            py[2 * 32 + lane] = y2;
            py[3 * 32 + lane] = y3;
        }
        barc(barid);                                 // BAR_B: PY ready

        // ---- phase 5: combine + log_softmax (warp = graph) ----------------
        {
            const float* py = smf + SB_PY / 4 + crew * 512 + wl * 32;
            float yy = py[0] ;
            yy += py[128]; yy += py[256]; yy += py[384];
            yy = (lane < NCLS) ? yy + smf[SB_B3 / 4 + lane] : -1e30f;
            // wait: py index must include lane
            // (recomputed below correctly)
            float y0 = smf[SB_PY / 4 + crew * 512 + 0 * 128 + wl * 32 + lane];
            float y1 = smf[SB_PY / 4 + crew * 512 + 1 * 128 + wl * 32 + lane];
            float y2 = smf[SB_PY / 4 + crew * 512 + 2 * 128 + wl * 32 + lane];
            float y3 = smf[SB_PY / 4 + crew * 512 + 3 * 128 + wl * 32 + lane];
            float logit = (lane < NCLS)
                        ? (y0 + y1) + (y2 + y3) + smf[SB_B3 / 4 + lane]
                        : -1e30f;
            float mx = logit;
            #pragma unroll
            for (int o = 16; o; o >>= 1)
                mx = fmaxf(mx, __shfl_xor_sync(0xffffffffu, mx, o));
            float e = (lane < NCLS) ? expf(logit - mx) : 0.f;
            float s = e;
            #pragma unroll
            for (int o = 16; o; o >>= 1)
                s += __shfl_xor_sync(0xffffffffu, s, o);
            if (lane < NCLS)
                out[(size_t)(t * 4 + wl) * NCLS + lane] = logit - mx - logf(s);
        }
        // PV WAR vs next P2: ordered by BAR_B; PY WAR vs next P4: BAR_A.
    }
}

extern "C" void kernel_launch(void* const* d_in, const int* in_sizes, int n_in,
                              void* d_out, int out_size) {
    const float* x   = (const float*)d_in[0];
    const float* W1  = (const float*)d_in[1];
    const float* b1  = (const float*)d_in[2];
    const float* g1  = (const float*)d_in[3];
    const float* be1 = (const float*)d_in[4];
    const float* m1  = (const float*)d_in[5];
    const float* v1  = (const float*)d_in[6];
    const float* W2  = (const float*)d_in[7];
    const float* b2  = (const float*)d_in[8];
    const float* g2  = (const float*)d_in[9];
    const float* be2 = (const float*)d_in[10];
    const float* m2  = (const float*)d_in[11];
    const float* v2  = (const float*)d_in[12];
    const float* W3  = (const float*)d_in[13];
    const float* b3  = (const float*)d_in[14];

    cudaFuncSetAttribute(gcn_crew_kernel,
                         cudaFuncAttributeMaxDynamicSharedMemorySize, SB_TOT);
    gcn_crew_kernel<<<GRID, 256, SB_TOT>>>(
        x, W1, b1, g1, be1, m1, v1,
        W2, b2, g2, be2, m2, v2, W3, b3, (float*)d_out);
}

// round 9
// speedup vs baseline: 1.0284x; 1.0284x over previous
#include <cuda_runtime.h>
#include <cuda_fp16.h>
#include <math.h>

// ---------------------------------------------------------------------------
// Fused 3-layer GCN, fixed 21-node hand skeleton, 50000 graphs.
// R9 = R7 skeleton (8-graph tile, 3 barriers, 3 CTAs/SM) minus instructions:
//   * 24-col padding per graph -> epilogue is select-free, weights hoisted
//   * B fragments via ldmatrix.x4 (half the ldsm instructions)
//   * XOR-swizzled 128B rows (bases precomputed; keeps W3 in smem)
// ---------------------------------------------------------------------------

#define NODES   21
#define NCLS    29
#define NTILES  6250          // 50000 / 8
#define GRID    444           // 148 SM x 3 CTA
#define R2C     0.70710678118654752440f
#define WROOT   4.535533905932737f

// ---- smem byte offsets ----------------------------------------------------
#define SB_H    0             // h1mix fp16 [192 rows][128B] swizzled  24576
#define SB_A    24576         // W2'*s2 fp16 [128 j][128B] swizzled    16384
#define SB_W3   40960         // W3 [128 j][29 c] f32 (packed)         14848
#define SB_PV   55808         // pooled v [128 j][8 g] f32             4096
#define SB_PY   59904         // partial y [8 w][8 g][32 c] f32        8192
#define SB_T2   68096         // 128 f32
#define SB_B3   68608         // 32 f32
#define SB_C    68736         // W1 [3][64] f32                        768
#define SB_S1   69504         // 64 f32
#define SB_T1   69760         // 64 f32
#define SB_TOT  70016         // x3 CTA = 210,048 <= 228KB carveout

// ---- PTX helpers ----------------------------------------------------------
__device__ __forceinline__ unsigned smem_u32(const void* p) {
    unsigned a;
    asm("{ .reg .u64 t; cvta.to.shared.u64 t, %1; cvt.u32.u64 %0, t; }"
        : "=r"(a) : "l"(p));
    return a;
}
__device__ __forceinline__ void ldsm4(unsigned& r0, unsigned& r1,
                                      unsigned& r2, unsigned& r3, unsigned a) {
    asm volatile("ldmatrix.sync.aligned.m8n8.x4.shared.b16 {%0,%1,%2,%3}, [%4];"
                 : "=r"(r0), "=r"(r1), "=r"(r2), "=r"(r3) : "r"(a));
}
__device__ __forceinline__ void mma16816(float* c, const unsigned* a,
                                         unsigned b0, unsigned b1) {
    asm volatile(
        "mma.sync.aligned.m16n8k16.row.col.f32.f16.f16.f32 "
        "{%0,%1,%2,%3}, {%4,%5,%6,%7}, {%8,%9}, {%0,%1,%2,%3};"
        : "+f"(c[0]), "+f"(c[1]), "+f"(c[2]), "+f"(c[3])
        : "r"(a[0]), "r"(a[1]), "r"(a[2]), "r"(a[3]), "r"(b0), "r"(b1));
}
__device__ __forceinline__ float wpool(int l) {  // node weight * (1/21); pad=0
    if (l == 0)  return WROOT / 21.f;
    if (l >= 21) return 0.f;
    return ((l & 3) == 0) ? (0.5f / 21.f) : (1.0f / 21.f);
}
__device__ __forceinline__ float pick4(const float* v, int s) {
    return (s == 0) ? v[0] : (s == 1) ? v[1] : (s == 2) ? v[2] : v[3];
}

// ---------------------------------------------------------------------------
__global__ void __launch_bounds__(256, 3)
gcn_r9_kernel(const float* __restrict__ x,
              const float* __restrict__ W1, const float* __restrict__ b1,
              const float* __restrict__ g1, const float* __restrict__ be1,
              const float* __restrict__ m1, const float* __restrict__ v1,
              const float* __restrict__ W2, const float* __restrict__ b2,
              const float* __restrict__ g2, const float* __restrict__ be2,
              const float* __restrict__ m2, const float* __restrict__ v2,
              const float* __restrict__ W3, const float* __restrict__ b3,
              float* __restrict__ out) {
    extern __shared__ char smc[];
    float* smf = (float*)smc;
    const unsigned sb = smem_u32(smc);
    const int tid  = threadIdx.x;
    const int lane = tid & 31;
    const int wid  = tid >> 5;          // 0..7
    const int jq   = wid & 3;           // j-strip of 32
    const int half = wid >> 2;          // 0: graphs 0-3, 1: graphs 4-7

    // ---------------- staging (once per CTA) -------------------------------
    for (int i = tid; i < 8192; i += 256) {          // A = W2^T*diag(s2), swz
        int j = i & 127, k = i >> 7;
        float s = g2[j] * rsqrtf(v2[j] + 1e-5f);
        int off = SB_A + j * 128 + (((k >> 3) ^ (j & 7)) << 4) + (k & 7) * 2;
        *(__half*)(smc + off) = __float2half(W2[k * 128 + j] * s);
    }
    for (int i = tid; i < 128 * NCLS; i += 256)      // W3 raw, packed [128][29]
        smf[SB_W3 / 4 + i] = W3[i];
    for (int i = tid; i < 768; i += 256) {           // zero H pad rows n=21..23
        int g = i / 96, rem = i % 96;
        int row = 24 * g + 21 + rem / 32;
        *(float*)(smc + SB_H + row * 128 + (rem % 32) * 4) = 0.f;
    }
    if (tid < 128) {
        float s = g2[tid] * rsqrtf(v2[tid] + 1e-5f);
        smf[SB_T2 / 4 + tid] = (b2[tid] - m2[tid]) * s + be2[tid];
    }
    if (tid < NCLS) smf[SB_B3 / 4 + tid] = b3[tid];
    for (int i = tid; i < 192; i += 256) smf[SB_C / 4 + i] = W1[i];
    if (tid < 64) {
        float s = g1[tid] * rsqrtf(v1[tid] + 1e-5f);
        smf[SB_S1 / 4 + tid] = s;
        smf[SB_T1 / 4 + tid] = (b1[tid] - m1[tid]) * s + be1[tid];
    }
    __syncthreads();

    // ---- per-warp invariants ---------------------------------------------
    float t2r[4];
    #pragma unroll
    for (int r = 0; r < 4; ++r)
        t2r[r] = smf[SB_T2 / 4 + 32 * jq + (lane >> 2) + 8 * r];
    const int cp2 = 2 * (lane & 3);
    float pw0[3], pw1[3];                 // pooled weights, hoisted
    #pragma unroll
    for (int p = 0; p < 3; ++p) {
        pw0[p] = wpool(8 * p + cp2);
        pw1[p] = wpool(8 * p + cp2 + 1);
    }
    // B ldsm4 bases (c = k32 chunk 0/1), swizzle folded in; inner += nt*1024
    unsigned bB[2];
    #pragma unroll
    for (int c = 0; c < 2; ++c)
        bB[c] = sb + SB_H + (96 * half + (lane & 7)) * 128
              + ((((lane >> 3) + 4 * c) ^ (lane & 7)) << 4);

    // A fragments: static across all tiles -> load ONCE (32 regs)
    unsigned ah[4][2][4];
    #pragma unroll
    for (int kk = 0; kk < 4; ++kk)
        #pragma unroll
        for (int mt = 0; mt < 2; ++mt) {
            int row = 32 * jq + 16 * mt + (lane & 15);
            ldsm4(ah[kk][mt][0], ah[kk][mt][1], ah[kk][mt][2], ah[kk][mt][3],
                  sb + SB_A + row * 128
                  + ((((lane >> 4) + 2 * kk) ^ (row & 7)) << 4));
        }

    for (int tile = blockIdx.x; tile < NTILES; tile += GRID) {
        const int gbase = tile * 8;

        // ---- phase 1: layer 1 + mix + BN + ReLU + mix2 -> H (warp=graph) --
        {
            const float2 w1a = ((const float2*)(smf + SB_C / 4))[lane];
            const float2 w1b = ((const float2*)(smf + SB_C / 4 + 64))[lane];
            const float2 w1c = ((const float2*)(smf + SB_C / 4 + 128))[lane];
            const float2 s1  = ((const float2*)(smf + SB_S1 / 4))[lane];
            const float2 t1  = ((const float2*)(smf + SB_T1 / 4))[lane];
            const float* xg = x + (size_t)(gbase + wid) * 63;
            const float xv0 = xg[lane];
            const float xv1 = (lane < 31) ? xg[32 + lane] : 0.f;
            const int rb = 24 * wid;
            const int c4 = lane >> 2;
            const int lo = (lane & 3) * 4;

            float2 z0, h0;
            {
                float xa = __shfl_sync(0xffffffffu, xv0, 0);
                float xb = __shfl_sync(0xffffffffu, xv0, 1);
                float xc = __shfl_sync(0xffffffffu, xv0, 2);
                z0.x = fmaf(xa, w1a.x, fmaf(xb, w1b.x, xc * w1c.x));
                z0.y = fmaf(xa, w1a.y, fmaf(xb, w1b.y, xc * w1c.y));
                h0.x = fmaxf(fmaf(z0.x, s1.x, t1.x), 0.f);
                h0.y = fmaxf(fmaf(z0.y, s1.y, t1.y), 0.f);
                *(__half2*)(smc + SB_H + rb * 128 + ((c4 ^ (rb & 7)) << 4) + lo)
                    = __floats2half2_rn(h0.x, h0.y);
            }
            #pragma unroll
            for (int f = 0; f < 5; ++f) {
                float2 zp = z0, hp = h0;
                #pragma unroll
                for (int i = 0; i < 4; ++i) {
                    const int n = 1 + 4 * f + i;
                    const float cp = (i == 0) ? R2C : 0.5f;
                    const int i0 = 3 * n;
                    float xa = (i0 < 32) ? __shfl_sync(0xffffffffu, xv0, i0)
                                         : __shfl_sync(0xffffffffu, xv1, i0 - 32);
                    float xb = (i0 + 1 < 32) ? __shfl_sync(0xffffffffu, xv0, i0 + 1)
                                             : __shfl_sync(0xffffffffu, xv1, i0 - 31);
                    float xc = (i0 + 2 < 32) ? __shfl_sync(0xffffffffu, xv0, i0 + 2)
                                             : __shfl_sync(0xffffffffu, xv1, i0 - 30);
                    float2 zn, hn;
                    zn.x = fmaf(xa, w1a.x, fmaf(xb, w1b.x, xc * w1c.x));
                    zn.y = fmaf(xa, w1a.y, fmaf(xb, w1b.y, xc * w1c.y));
                    float m1x = fmaf(0.5f, zn.x, cp * zp.x);
                    float m1y = fmaf(0.5f, zn.y, cp * zp.y);
                    hn.x = fmaxf(fmaf(m1x, s1.x, t1.x), 0.f);
                    hn.y = fmaxf(fmaf(m1y, s1.y, t1.y), 0.f);
                    float m2x = fmaf(0.5f, hn.x, cp * hp.x);
                    float m2y = fmaf(0.5f, hn.y, cp * hp.y);
                    const int row = rb + n;
                    *(__half2*)(smc + SB_H + row * 128
                                + ((c4 ^ (row & 7)) << 4) + lo)
                        = __floats2half2_rn(m2x, m2y);
                    zp = zn; hp = hn;
                }
            }
        }
        __syncthreads();                              // BAR1: H ready

        // ---- phase 2+3: MMA (M=32, 12 nt) + select-free pooling -----------
        {
            float v[4][4];
            #pragma unroll
            for (int r = 0; r < 4; ++r)
                #pragma unroll
                for (int g = 0; g < 4; ++g) v[r][g] = 0.f;

            #pragma unroll
            for (int nt = 0; nt < 12; ++nt) {
                float acc[8] = {0.f,0.f,0.f,0.f,0.f,0.f,0.f,0.f};
                unsigned b[8];
                ldsm4(b[0], b[1], b[2], b[3], bB[0] + nt * 1024);
                ldsm4(b[4], b[5], b[6], b[7], bB[1] + nt * 1024);
                #pragma unroll
                for (int kk = 0; kk < 4; ++kk) {
                    mma16816(acc,     ah[kk][0], b[2 * kk], b[2 * kk + 1]);
                    mma16816(acc + 4, ah[kk][1], b[2 * kk], b[2 * kk + 1]);
                }
                const int g = nt / 3, p = nt % 3;     // compile-time
                const float w0 = pw0[p], w1 = pw1[p];
                #pragma unroll
                for (int r = 0; r < 4; ++r) {
                    float q0 = fmaxf(acc[2 * r]     + t2r[r], 0.f) * w0;
                    float q1 = fmaxf(acc[2 * r + 1] + t2r[r], 0.f) * w1;
                    v[r][g] += q0 + q1;
                }
            }
            #pragma unroll
            for (int r = 0; r < 4; ++r)
                #pragma unroll
                for (int g = 0; g < 4; ++g) {
                    v[r][g] += __shfl_xor_sync(0xffffffffu, v[r][g], 1);
                    v[r][g] += __shfl_xor_sync(0xffffffffu, v[r][g], 2);
                }
            const int gs = lane & 3;
            #pragma unroll
            for (int r = 0; r < 4; ++r) {
                const int j = 32 * jq + (lane >> 2) + 8 * r;
                smf[SB_PV / 4 + j * 8 + 4 * half + gs] = pick4(v[r], gs);
            }
        }
        __syncthreads();                              // BAR2: PV ready

        // ---- phase 4: layer 3 partial over j-strip ------------------------
        {
            float y[8];
            #pragma unroll
            for (int g = 0; g < 8; ++g) y[g] = 0.f;
            #pragma unroll
            for (int jj = 0; jj < 16; ++jj) {
                const int j = 16 * wid + jj;
                float wc = (lane < NCLS) ? smf[SB_W3 / 4 + j * NCLS + lane] : 0.f;
                float4 p0 = *(const float4*)(smf + SB_PV / 4 + j * 8);
                float4 p1 = *(const float4*)(smf + SB_PV / 4 + j * 8 + 4);
                y[0] = fmaf(p0.x, wc, y[0]); y[1] = fmaf(p0.y, wc, y[1]);
                y[2] = fmaf(p0.z, wc, y[2]); y[3] = fmaf(p0.w, wc, y[3]);
                y[4] = fmaf(p1.x, wc, y[4]); y[5] = fmaf(p1.y, wc, y[5]);
                y[6] = fmaf(p1.z, wc, y[6]); y[7] = fmaf(p1.w, wc, y[7]);
            }
            #pragma unroll
            for (int g = 0; g < 8; ++g)
                smf[SB_PY / 4 + wid * 256 + g * 32 + lane] = y[g];
        }
        __syncthreads();                              // BAR3: PY ready

        // ---- phase 5: combine + log_softmax (warp = graph) ----------------
        {
            float yy = 0.f;
            #pragma unroll
            for (int w = 0; w < 8; ++w)
                yy += smf[SB_PY / 4 + w * 256 + wid * 32 + lane];
            float logit = (lane < NCLS) ? yy + smf[SB_B3 / 4 + lane] : -1e30f;
            float mx = logit;
            #pragma unroll
            for (int o = 16; o; o >>= 1)
                mx = fmaxf(mx, __shfl_xor_sync(0xffffffffu, mx, o));
            float e = (lane < NCLS) ? expf(logit - mx) : 0.f;
            float s = e;
            #pragma unroll
            for (int o = 16; o; o >>= 1)
                s += __shfl_xor_sync(0xffffffffu, s, o);
            if (lane < NCLS)
                out[(size_t)(gbase + wid) * NCLS + lane] = logit - mx - logf(s);
        }
        // H/PV/PY cross-tile hazards ordered by the BAR1..BAR3 chain
    }
}

extern "C" void kernel_launch(void* const* d_in, const int* in_sizes, int n_in,
                              void* d_out, int out_size) {
    const float* x   = (const float*)d_in[0];
    const float* W1  = (const float*)d_in[1];
    const float* b1  = (const float*)d_in[2];
    const float* g1  = (const float*)d_in[3];
    const float* be1 = (const float*)d_in[4];
    const float* m1  = (const float*)d_in[5];
    const float* v1  = (const float*)d_in[6];
    const float* W2  = (const float*)d_in[7];
    const float* b2  = (const float*)d_in[8];
    const float* g2  = (const float*)d_in[9];
    const float* be2 = (const float*)d_in[10];
    const float* m2  = (const float*)d_in[11];
    const float* v2  = (const float*)d_in[12];
    const float* W3  = (const float*)d_in[13];
    const float* b3  = (const float*)d_in[14];

    cudaFuncSetAttribute(gcn_r9_kernel,
                         cudaFuncAttributeMaxDynamicSharedMemorySize, SB_TOT);
    gcn_r9_kernel<<<GRID, 256, SB_TOT>>>(
        x, W1, b1, g1, be1, m1, v1,
        W2, b2, g2, be2, m2, v2, W3, b3, (float*)d_out);
}

// round 10
// speedup vs baseline: 1.1595x; 1.1275x over previous
#include <cuda_runtime.h>
#include <cuda_fp16.h>
#include <math.h>

// ---------------------------------------------------------------------------
// Fused 3-layer GCN, fixed 21-node hand skeleton, 50000 graphs.
// R10 = R9 skeleton, epilogues moved onto tensor cores:
//   * pooling via mma.m16n8k8: main-GEMM C-fragments repacked (cvt+hmax2)
//     as A-fragments against a static node-weight B matrix -> v lands as a
//     [j, graph] C-fragment, no shfl reduction
//   * layer 3 via mma.m16n8k16: k=128 split across 8 warps, W3/21 fragments
//     static in registers, v through smem as fp16 [g][j]
// ---------------------------------------------------------------------------

#define NODES   21
#define NCLS    29
#define NTILES  6250          // 50000 / 8
#define GRID    444           // 148 SM x 3 CTA
#define R2C     0.70710678118654752440f
#define WROOT   4.535533905932737f

// ---- smem byte offsets ----------------------------------------------------
#define SB_H    0             // h1mix fp16 [192 rows][128B] swizzled  24576
#define SB_A    24576         // W2'*s2 fp16 [128 j][128B] swizzled    16384
#define SB_BP   40960         // pool B [12 nt][8 n][8 k] fp16         1536
#define SB_VT   42496         // v fp16 [8 g][128 j]                   2048
#define SB_PY   44544         // partial y [8 w][8 g][32 c] f32        8192
#define SB_T2   52736         // 128 f32
#define SB_B3   53248         // 32 f32
#define SB_C    53376         // W1 [3][64] f32                        768
#define SB_S1   54144         // 64 f32
#define SB_T1   54400         // 64 f32
#define SB_TOT  54656         // x3 CTA = 163,968

// ---- PTX helpers ----------------------------------------------------------
__device__ __forceinline__ unsigned smem_u32(const void* p) {
    unsigned a;
    asm("{ .reg .u64 t; cvta.to.shared.u64 t, %1; cvt.u32.u64 %0, t; }"
        : "=r"(a) : "l"(p));
    return a;
}
__device__ __forceinline__ void ldsm4(unsigned& r0, unsigned& r1,
                                      unsigned& r2, unsigned& r3, unsigned a) {
    asm volatile("ldmatrix.sync.aligned.m8n8.x4.shared.b16 {%0,%1,%2,%3}, [%4];"
                 : "=r"(r0), "=r"(r1), "=r"(r2), "=r"(r3) : "r"(a));
}
__device__ __forceinline__ void ldsm1(unsigned& r0, unsigned a) {
    asm volatile("ldmatrix.sync.aligned.m8n8.x1.shared.b16 {%0}, [%1];"
                 : "=r"(r0) : "r"(a));
}
__device__ __forceinline__ void mma16816(float* c, const unsigned* a,
                                         unsigned b0, unsigned b1) {
    asm volatile(
        "mma.sync.aligned.m16n8k16.row.col.f32.f16.f16.f32 "
        "{%0,%1,%2,%3}, {%4,%5,%6,%7}, {%8,%9}, {%0,%1,%2,%3};"
        : "+f"(c[0]), "+f"(c[1]), "+f"(c[2]), "+f"(c[3])
        : "r"(a[0]), "r"(a[1]), "r"(a[2]), "r"(a[3]), "r"(b0), "r"(b1));
}
__device__ __forceinline__ void mma16808(float* c, unsigned a0, unsigned a1,
                                         unsigned b0) {
    asm volatile(
        "mma.sync.aligned.m16n8k8.row.col.f32.f16.f16.f32 "
        "{%0,%1,%2,%3}, {%4,%5}, {%6}, {%0,%1,%2,%3};"
        : "+f"(c[0]), "+f"(c[1]), "+f"(c[2]), "+f"(c[3])
        : "r"(a0), "r"(a1), "r"(b0));
}
__device__ __forceinline__ unsigned relupack(float a, float b) {
    __half2 h = __floats2half2_rn(a, b);            // x = a (k even), y = b
    h = __hmax2(h, __float2half2_rn(0.f));          // ReLU
    return *(unsigned*)&h;
}
__device__ __forceinline__ float wraw(int l) {      // raw pooled node weight
    if (l == 0)  return WROOT;
    if (l >= 21) return 0.f;
    return ((l & 3) == 0) ? 0.5f : 1.0f;
}

// ---------------------------------------------------------------------------
__global__ void __launch_bounds__(256, 3)
gcn_r10_kernel(const float* __restrict__ x,
               const float* __restrict__ W1, const float* __restrict__ b1,
               const float* __restrict__ g1, const float* __restrict__ be1,
               const float* __restrict__ m1, const float* __restrict__ v1,
               const float* __restrict__ W2, const float* __restrict__ b2,
               const float* __restrict__ g2, const float* __restrict__ be2,
               const float* __restrict__ m2, const float* __restrict__ v2,
               const float* __restrict__ W3, const float* __restrict__ b3,
               float* __restrict__ out) {
    extern __shared__ char smc[];
    float* smf = (float*)smc;
    const unsigned sb = smem_u32(smc);
    const int tid  = threadIdx.x;
    const int lane = tid & 31;
    const int wid  = tid >> 5;          // 0..7
    const int jq   = wid & 3;           // j-strip of 32
    const int half = wid >> 2;          // 0: graphs 0-3, 1: graphs 4-7
    const int lr   = lane >> 2;         // fragment row
    const int lc   = lane & 3;          // fragment col-pair

    // ---------------- staging (once per CTA) -------------------------------
    for (int i = tid; i < 8192; i += 256) {          // A = W2^T*diag(s2), swz
        int j = i & 127, k = i >> 7;
        float s = g2[j] * rsqrtf(v2[j] + 1e-5f);
        int off = SB_A + j * 128 + (((k >> 3) ^ (j & 7)) << 4) + (k & 7) * 2;
        *(__half*)(smc + off) = __float2half(W2[k * 128 + j] * s);
    }
    for (int i = tid; i < 768; i += 256) {           // pool B [nt][n][k]
        int nt = i >> 6, n = (i >> 3) & 7, k = i & 7;
        int col = 8 * nt + k;
        int gl = col / 24, ln = col % 24;
        float v_ = (n == gl) ? wraw(ln) : 0.f;
        *(__half*)(smc + SB_BP + nt * 128 + n * 16 + k * 2) = __float2half(v_);
    }
    for (int i = tid; i < 768; i += 256) {           // zero H pad rows n=21..23
        int g = i / 96, rem = i % 96;
        int row = 24 * g + 21 + rem / 32;
        *(float*)(smc + SB_H + row * 128 + (rem % 32) * 4) = 0.f;
    }
    if (tid < 128) {
        float s = g2[tid] * rsqrtf(v2[tid] + 1e-5f);
        smf[SB_T2 / 4 + tid] = (b2[tid] - m2[tid]) * s + be2[tid];
    }
    if (tid < NCLS) smf[SB_B3 / 4 + tid] = b3[tid];
    for (int i = tid; i < 192; i += 256) smf[SB_C / 4 + i] = W1[i];
    if (tid < 64) {
        float s = g1[tid] * rsqrtf(v1[tid] + 1e-5f);
        smf[SB_S1 / 4 + tid] = s;
        smf[SB_T1 / 4 + tid] = (b1[tid] - m1[tid]) * s + be1[tid];
    }
    __syncthreads();

    // ---- per-warp invariants ---------------------------------------------
    float t2r[4];
    #pragma unroll
    for (int r = 0; r < 4; ++r)
        t2r[r] = smf[SB_T2 / 4 + 32 * jq + lr + 8 * r];
    unsigned bB[2];
    #pragma unroll
    for (int c = 0; c < 2; ++c)
        bB[c] = sb + SB_H + (96 * half + (lane & 7)) * 128
              + ((((lane >> 3) + 4 * c) ^ (lane & 7)) << 4);
    const unsigned bpAddr = sb + SB_BP + (lane & 7) * 16;

    // main-GEMM A fragments (static W2 strip): load ONCE (32 regs)
    unsigned ah[4][2][4];
    #pragma unroll
    for (int kk = 0; kk < 4; ++kk)
        #pragma unroll
        for (int mt = 0; mt < 2; ++mt) {
            int row = 32 * jq + 16 * mt + (lane & 15);
            ldsm4(ah[kk][mt][0], ah[kk][mt][1], ah[kk][mt][2], ah[kk][mt][3],
                  sb + SB_A + row * 128
                  + ((((lane >> 4) + 2 * kk) ^ (row & 7)) << 4));
        }
    // layer-3 A fragments: W3^T/21, k-slice = j 16wid..16wid+15 (static)
    unsigned a3w[2][4];
    {
        const int j0 = 16 * wid;
        #pragma unroll
        for (int mt = 0; mt < 2; ++mt) {
            int cls0 = 16 * mt + lr, cls1 = cls0 + 8;
            float f00 = (cls0 < NCLS) ? W3[(j0 + 2 * lc) * NCLS + cls0] / 21.f : 0.f;
            float f01 = (cls0 < NCLS) ? W3[(j0 + 2 * lc + 1) * NCLS + cls0] / 21.f : 0.f;
            float f10 = (cls1 < NCLS) ? W3[(j0 + 2 * lc) * NCLS + cls1] / 21.f : 0.f;
            float f11 = (cls1 < NCLS) ? W3[(j0 + 2 * lc + 1) * NCLS + cls1] / 21.f : 0.f;
            float f20 = (cls0 < NCLS) ? W3[(j0 + 8 + 2 * lc) * NCLS + cls0] / 21.f : 0.f;
            float f21 = (cls0 < NCLS) ? W3[(j0 + 9 + 2 * lc) * NCLS + cls0] / 21.f : 0.f;
            float f30 = (cls1 < NCLS) ? W3[(j0 + 8 + 2 * lc) * NCLS + cls1] / 21.f : 0.f;
            float f31 = (cls1 < NCLS) ? W3[(j0 + 9 + 2 * lc) * NCLS + cls1] / 21.f : 0.f;
            __half2 h0 = __floats2half2_rn(f00, f01);
            __half2 h1 = __floats2half2_rn(f10, f11);
            __half2 h2v = __floats2half2_rn(f20, f21);
            __half2 h3 = __floats2half2_rn(f30, f31);
            a3w[mt][0] = *(unsigned*)&h0;
            a3w[mt][1] = *(unsigned*)&h1;
            a3w[mt][2] = *(unsigned*)&h2v;
            a3w[mt][3] = *(unsigned*)&h3;
        }
    }

    for (int tile = blockIdx.x; tile < NTILES; tile += GRID) {
        const int gbase = tile * 8;

        // ---- phase 1: layer 1 + mix + BN + ReLU + mix2 -> H (warp=graph) --
        {
            const float2 w1a = ((const float2*)(smf + SB_C / 4))[lane];
            const float2 w1b = ((const float2*)(smf + SB_C / 4 + 64))[lane];
            const float2 w1c = ((const float2*)(smf + SB_C / 4 + 128))[lane];
            const float2 s1  = ((const float2*)(smf + SB_S1 / 4))[lane];
            const float2 t1  = ((const float2*)(smf + SB_T1 / 4))[lane];
            const float* xg = x + (size_t)(gbase + wid) * 63;
            const float xv0 = xg[lane];
            const float xv1 = (lane < 31) ? xg[32 + lane] : 0.f;
            const int rb = 24 * wid;
            const int c4 = lane >> 2;
            const int lo = (lane & 3) * 4;

            float2 z0, h0;
            {
                float xa = __shfl_sync(0xffffffffu, xv0, 0);
                float xb = __shfl_sync(0xffffffffu, xv0, 1);
                float xc = __shfl_sync(0xffffffffu, xv0, 2);
                z0.x = fmaf(xa, w1a.x, fmaf(xb, w1b.x, xc * w1c.x));
                z0.y = fmaf(xa, w1a.y, fmaf(xb, w1b.y, xc * w1c.y));
                h0.x = fmaxf(fmaf(z0.x, s1.x, t1.x), 0.f);
                h0.y = fmaxf(fmaf(z0.y, s1.y, t1.y), 0.f);
                *(__half2*)(smc + SB_H + rb * 128 + ((c4 ^ (rb & 7)) << 4) + lo)
                    = __floats2half2_rn(h0.x, h0.y);
            }
            #pragma unroll
            for (int f = 0; f < 5; ++f) {
                float2 zp = z0, hp = h0;
                #pragma unroll
                for (int i = 0; i < 4; ++i) {
                    const int n = 1 + 4 * f + i;
                    const float cp = (i == 0) ? R2C : 0.5f;
                    const int i0 = 3 * n;
                    float xa = (i0 < 32) ? __shfl_sync(0xffffffffu, xv0, i0)
                                         : __shfl_sync(0xffffffffu, xv1, i0 - 32);
                    float xb = (i0 + 1 < 32) ? __shfl_sync(0xffffffffu, xv0, i0 + 1)
                                             : __shfl_sync(0xffffffffu, xv1, i0 - 31);
                    float xc = (i0 + 2 < 32) ? __shfl_sync(0xffffffffu, xv0, i0 + 2)
                                             : __shfl_sync(0xffffffffu, xv1, i0 - 30);
                    float2 zn, hn;
                    zn.x = fmaf(xa, w1a.x, fmaf(xb, w1b.x, xc * w1c.x));
                    zn.y = fmaf(xa, w1a.y, fmaf(xb, w1b.y, xc * w1c.y));
                    float m1x = fmaf(0.5f, zn.x, cp * zp.x);
                    float m1y = fmaf(0.5f, zn.y, cp * zp.y);
                    hn.x = fmaxf(fmaf(m1x, s1.x, t1.x), 0.f);
                    hn.y = fmaxf(fmaf(m1y, s1.y, t1.y), 0.f);
                    float m2x = fmaf(0.5f, hn.x, cp * hp.x);
                    float m2y = fmaf(0.5f, hn.y, cp * hp.y);
                    const int row = rb + n;
                    *(__half2*)(smc + SB_H + row * 128
                                + ((c4 ^ (row & 7)) << 4) + lo)
                        = __floats2half2_rn(m2x, m2y);
                    zp = zn; hp = hn;
                }
            }
        }
        __syncthreads();                              // BAR1: H ready

        // ---- phase 2: MMA (M=32, 12 nt) + MMA pooling ---------------------
        {
            float vC[2][4];
            #pragma unroll
            for (int mt = 0; mt < 2; ++mt)
                #pragma unroll
                for (int q = 0; q < 4; ++q) vC[mt][q] = 0.f;

            #pragma unroll
            for (int nt = 0; nt < 12; ++nt) {
                float acc[8] = {0.f,0.f,0.f,0.f,0.f,0.f,0.f,0.f};
                unsigned b[8];
                ldsm4(b[0], b[1], b[2], b[3], bB[0] + nt * 1024);
                ldsm4(b[4], b[5], b[6], b[7], bB[1] + nt * 1024);
                #pragma unroll
                for (int kk = 0; kk < 4; ++kk) {
                    mma16816(acc,     ah[kk][0], b[2 * kk], b[2 * kk + 1]);
                    mma16816(acc + 4, ah[kk][1], b[2 * kk], b[2 * kk + 1]);
                }
                unsigned bp;
                ldsm1(bp, bpAddr + nt * 128);
                #pragma unroll
                for (int mt = 0; mt < 2; ++mt) {
                    unsigned pa0 = relupack(acc[4 * mt]     + t2r[2 * mt],
                                            acc[4 * mt + 1] + t2r[2 * mt]);
                    unsigned pa1 = relupack(acc[4 * mt + 2] + t2r[2 * mt + 1],
                                            acc[4 * mt + 3] + t2r[2 * mt + 1]);
                    mma16808(vC[mt], pa0, pa1, bp);
                }
            }
            // store v as fp16 [g][j] (threads with lc<2 hold the 4 graphs)
            if (lc < 2) {
                #pragma unroll
                for (int mt = 0; mt < 2; ++mt) {
                    const int j = 32 * jq + 16 * mt + lr;
                    const int g0 = 4 * half + 2 * lc;
                    *(__half*)(smc + SB_VT + g0 * 256 + j * 2)
                        = __float2half(vC[mt][0]);
                    *(__half*)(smc + SB_VT + (g0 + 1) * 256 + j * 2)
                        = __float2half(vC[mt][1]);
                    *(__half*)(smc + SB_VT + g0 * 256 + (j + 8) * 2)
                        = __float2half(vC[mt][2]);
                    *(__half*)(smc + SB_VT + (g0 + 1) * 256 + (j + 8) * 2)
                        = __float2half(vC[mt][3]);
                }
            }
        }
        __syncthreads();                              // BAR2: VT ready

        // ---- phase 4: layer 3 via MMA (k-slice = 16 j per warp) -----------
        {
            const int j0 = 16 * wid;
            unsigned bv0 = *(unsigned*)(smc + SB_VT + lr * 256 + (j0 + 2 * lc) * 2);
            unsigned bv1 = *(unsigned*)(smc + SB_VT + lr * 256 + (j0 + 8 + 2 * lc) * 2);
            float yc[8] = {0.f,0.f,0.f,0.f,0.f,0.f,0.f,0.f};
            mma16816(yc,     a3w[0], bv0, bv1);
            mma16816(yc + 4, a3w[1], bv0, bv1);
            float* py = smf + SB_PY / 4 + wid * 256;
            #pragma unroll
            for (int mt = 0; mt < 2; ++mt) {
                py[(2 * lc)     * 32 + 16 * mt + lr]     = yc[4 * mt];
                py[(2 * lc + 1) * 32 + 16 * mt + lr]     = yc[4 * mt + 1];
                py[(2 * lc)     * 32 + 16 * mt + lr + 8] = yc[4 * mt + 2];
                py[(2 * lc + 1) * 32 + 16 * mt + lr + 8] = yc[4 * mt + 3];
            }
        }
        __syncthreads();                              // BAR3: PY ready

        // ---- phase 5: combine + log_softmax (warp = graph) ----------------
        {
            float yy = 0.f;
            #pragma unroll
            for (int w = 0; w < 8; ++w)
                yy += smf[SB_PY / 4 + w * 256 + wid * 32 + lane];
            float logit = (lane < NCLS) ? yy + smf[SB_B3 / 4 + lane] : -1e30f;
            float mx = logit;
            #pragma unroll
            for (int o = 16; o; o >>= 1)
                mx = fmaxf(mx, __shfl_xor_sync(0xffffffffu, mx, o));
            float e = (lane < NCLS) ? expf(logit - mx) : 0.f;
            float s = e;
            #pragma unroll
            for (int o = 16; o; o >>= 1)
                s += __shfl_xor_sync(0xffffffffu, s, o);
            if (lane < NCLS)
                out[(size_t)(gbase + wid) * NCLS + lane] = logit - mx - logf(s);
        }
        // H/VT/PY cross-tile hazards ordered by the BAR1..BAR3 chain
    }
}

extern "C" void kernel_launch(void* const* d_in, const int* in_sizes, int n_in,
                              void* d_out, int out_size) {
    const float* x   = (const float*)d_in[0];
    const float* W1  = (const float*)d_in[1];
    const float* b1  = (const float*)d_in[2];
    const float* g1  = (const float*)d_in[3];
    const float* be1 = (const float*)d_in[4];
    const float* m1  = (const float*)d_in[5];
    const float* v1  = (const float*)d_in[6];
    const float* W2  = (const float*)d_in[7];
    const float* b2  = (const float*)d_in[8];
    const float* g2  = (const float*)d_in[9];
    const float* be2 = (const float*)d_in[10];
    const float* m2  = (const float*)d_in[11];
    const float* v2  = (const float*)d_in[12];
    const float* W3  = (const float*)d_in[13];
    const float* b3  = (const float*)d_in[14];

    cudaFuncSetAttribute(gcn_r10_kernel,
                         cudaFuncAttributeMaxDynamicSharedMemorySize, SB_TOT);
    gcn_r10_kernel<<<GRID, 256, SB_TOT>>>(
        x, W1, b1, g1, be1, m1, v1,
        W2, b2, g2, be2, m2, v2, W3, b3, (float*)d_out);
}

// round 11
// speedup vs baseline: 1.2615x; 1.0880x over previous
#include <cuda_runtime.h>
#include <cuda_fp16.h>
#include <math.h>

// ---------------------------------------------------------------------------
// Fused 3-layer GCN, fixed 21-node hand skeleton, 50000 graphs.
// R11 = R10 (MMA pooling + MMA layer-3) with scalar phases SIMD-ized:
//   * phase-1 mix/BN/ReLU/mix chain in half2 (HFMA2/HMUL2/HMAX2)
//   * phase-2 t2-add + ReLU in half2 (HADD2+HMAX2 after pack)
//   * softmax via __expf/__logf (MUFU)
// ---------------------------------------------------------------------------

#define NODES   21
#define NCLS    29
#define NTILES  6250          // 50000 / 8
#define GRID    444           // 148 SM x 3 CTA
#define R2C     0.70710678118654752440f
#define WROOT   4.535533905932737f

// ---- smem byte offsets ----------------------------------------------------
#define SB_H    0             // h1mix fp16 [192 rows][128B] swizzled  24576
#define SB_A    24576         // W2'*s2 fp16 [128 j][128B] swizzled    16384
#define SB_BP   40960         // pool B [12 nt][8 n][8 k] fp16         1536
#define SB_VT   42496         // v fp16 [8 g][128 j]                   2048
#define SB_PY   44544         // partial y [8 w][8 g][32 c] f32        8192
#define SB_T2   52736         // 128 f32
#define SB_B3   53248         // 32 f32
#define SB_C    53376         // W1 [3][64] f32                        768
#define SB_S1   54144         // s1 half2 [32]                         128
#define SB_T1   54400         // t1 half2 [32]                         128
#define SB_TOT  54656         // x3 CTA = 163,968

// ---- PTX helpers ----------------------------------------------------------
__device__ __forceinline__ unsigned smem_u32(const void* p) {
    unsigned a;
    asm("{ .reg .u64 t; cvta.to.shared.u64 t, %1; cvt.u32.u64 %0, t; }"
        : "=r"(a) : "l"(p));
    return a;
}
__device__ __forceinline__ void ldsm4(unsigned& r0, unsigned& r1,
                                      unsigned& r2, unsigned& r3, unsigned a) {
    asm volatile("ldmatrix.sync.aligned.m8n8.x4.shared.b16 {%0,%1,%2,%3}, [%4];"
                 : "=r"(r0), "=r"(r1), "=r"(r2), "=r"(r3) : "r"(a));
}
__device__ __forceinline__ void ldsm1(unsigned& r0, unsigned a) {
    asm volatile("ldmatrix.sync.aligned.m8n8.x1.shared.b16 {%0}, [%1];"
                 : "=r"(r0) : "r"(a));
}
__device__ __forceinline__ void mma16816(float* c, const unsigned* a,
                                         unsigned b0, unsigned b1) {
    asm volatile(
        "mma.sync.aligned.m16n8k16.row.col.f32.f16.f16.f32 "
        "{%0,%1,%2,%3}, {%4,%5,%6,%7}, {%8,%9}, {%0,%1,%2,%3};"
        : "+f"(c[0]), "+f"(c[1]), "+f"(c[2]), "+f"(c[3])
        : "r"(a[0]), "r"(a[1]), "r"(a[2]), "r"(a[3]), "r"(b0), "r"(b1));
}
__device__ __forceinline__ void mma16808(float* c, unsigned a0, unsigned a1,
                                         unsigned b0) {
    asm volatile(
        "mma.sync.aligned.m16n8k8.row.col.f32.f16.f16.f32 "
        "{%0,%1,%2,%3}, {%4,%5}, {%6}, {%0,%1,%2,%3};"
        : "+f"(c[0]), "+f"(c[1]), "+f"(c[2]), "+f"(c[3])
        : "r"(a0), "r"(a1), "r"(b0));
}
__device__ __forceinline__ unsigned relupack2(float a, float b, __half2 t) {
    __half2 h = __floats2half2_rn(a, b);
    h = __hmax2(__hadd2(h, t), __float2half2_rn(0.f));
    return *(unsigned*)&h;
}
__device__ __forceinline__ float wraw(int l) {      // raw pooled node weight
    if (l == 0)  return WROOT;
    if (l >= 21) return 0.f;
    return ((l & 3) == 0) ? 0.5f : 1.0f;
}

// ---------------------------------------------------------------------------
__global__ void __launch_bounds__(256, 3)
gcn_r11_kernel(const float* __restrict__ x,
               const float* __restrict__ W1, const float* __restrict__ b1,
               const float* __restrict__ g1, const float* __restrict__ be1,
               const float* __restrict__ m1, const float* __restrict__ v1,
               const float* __restrict__ W2, const float* __restrict__ b2,
               const float* __restrict__ g2, const float* __restrict__ be2,
               const float* __restrict__ m2, const float* __restrict__ v2,
               const float* __restrict__ W3, const float* __restrict__ b3,
               float* __restrict__ out) {
    extern __shared__ char smc[];
    float* smf = (float*)smc;
    const unsigned sb = smem_u32(smc);
    const int tid  = threadIdx.x;
    const int lane = tid & 31;
    const int wid  = tid >> 5;          // 0..7
    const int jq   = wid & 3;           // j-strip of 32
    const int half = wid >> 2;          // 0: graphs 0-3, 1: graphs 4-7
    const int lr   = lane >> 2;         // fragment row
    const int lc   = lane & 3;          // fragment col-pair

    // ---------------- staging (once per CTA) -------------------------------
    for (int i = tid; i < 8192; i += 256) {          // A = W2^T*diag(s2), swz
        int j = i & 127, k = i >> 7;
        float s = g2[j] * rsqrtf(v2[j] + 1e-5f);
        int off = SB_A + j * 128 + (((k >> 3) ^ (j & 7)) << 4) + (k & 7) * 2;
        *(__half*)(smc + off) = __float2half(W2[k * 128 + j] * s);
    }
    for (int i = tid; i < 768; i += 256) {           // pool B [nt][n][k]
        int nt = i >> 6, n = (i >> 3) & 7, k = i & 7;
        int col = 8 * nt + k;
        int gl = col / 24, ln = col % 24;
        float v_ = (n == gl) ? wraw(ln) : 0.f;
        *(__half*)(smc + SB_BP + nt * 128 + n * 16 + k * 2) = __float2half(v_);
    }
    for (int i = tid; i < 768; i += 256) {           // zero H pad rows n=21..23
        int g = i / 96, rem = i % 96;
        int row = 24 * g + 21 + rem / 32;
        *(float*)(smc + SB_H + row * 128 + (rem % 32) * 4) = 0.f;
    }
    if (tid < 128) {
        float s = g2[tid] * rsqrtf(v2[tid] + 1e-5f);
        smf[SB_T2 / 4 + tid] = (b2[tid] - m2[tid]) * s + be2[tid];
    }
    if (tid < NCLS) smf[SB_B3 / 4 + tid] = b3[tid];
    for (int i = tid; i < 192; i += 256) smf[SB_C / 4 + i] = W1[i];
    if (tid < 32) {                                  // s1/t1 as half2 pairs
        int c2 = 2 * tid;
        float sa = g1[c2] * rsqrtf(v1[c2] + 1e-5f);
        float sbv = g1[c2 + 1] * rsqrtf(v1[c2 + 1] + 1e-5f);
        float ta = (b1[c2] - m1[c2]) * sa + be1[c2];
        float tb = (b1[c2 + 1] - m1[c2 + 1]) * sbv + be1[c2 + 1];
        ((__half2*)(smc + SB_S1))[tid] = __floats2half2_rn(sa, sbv);
        ((__half2*)(smc + SB_T1))[tid] = __floats2half2_rn(ta, tb);
    }
    __syncthreads();

    // ---- per-warp invariants ---------------------------------------------
    __half2 t2h[4];
    #pragma unroll
    for (int r = 0; r < 4; ++r)
        t2h[r] = __float2half2_rn(smf[SB_T2 / 4 + 32 * jq + lr + 8 * r]);
    unsigned bB[2];
    #pragma unroll
    for (int c = 0; c < 2; ++c)
        bB[c] = sb + SB_H + (96 * half + (lane & 7)) * 128
              + ((((lane >> 3) + 4 * c) ^ (lane & 7)) << 4);
    const unsigned bpAddr = sb + SB_BP + (lane & 7) * 16;

    // main-GEMM A fragments (static W2 strip): load ONCE (32 regs)
    unsigned ah[4][2][4];
    #pragma unroll
    for (int kk = 0; kk < 4; ++kk)
        #pragma unroll
        for (int mt = 0; mt < 2; ++mt) {
            int row = 32 * jq + 16 * mt + (lane & 15);
            ldsm4(ah[kk][mt][0], ah[kk][mt][1], ah[kk][mt][2], ah[kk][mt][3],
                  sb + SB_A + row * 128
                  + ((((lane >> 4) + 2 * kk) ^ (row & 7)) << 4));
        }
    // layer-3 A fragments: W3^T/21, k-slice = j 16wid..16wid+15 (static)
    unsigned a3w[2][4];
    {
        const int j0 = 16 * wid;
        #pragma unroll
        for (int mt = 0; mt < 2; ++mt) {
            int cls0 = 16 * mt + lr, cls1 = cls0 + 8;
            float f00 = (cls0 < NCLS) ? W3[(j0 + 2 * lc) * NCLS + cls0] / 21.f : 0.f;
            float f01 = (cls0 < NCLS) ? W3[(j0 + 2 * lc + 1) * NCLS + cls0] / 21.f : 0.f;
            float f10 = (cls1 < NCLS) ? W3[(j0 + 2 * lc) * NCLS + cls1] / 21.f : 0.f;
            float f11 = (cls1 < NCLS) ? W3[(j0 + 2 * lc + 1) * NCLS + cls1] / 21.f : 0.f;
            float f20 = (cls0 < NCLS) ? W3[(j0 + 8 + 2 * lc) * NCLS + cls0] / 21.f : 0.f;
            float f21 = (cls0 < NCLS) ? W3[(j0 + 9 + 2 * lc) * NCLS + cls0] / 21.f : 0.f;
            float f30 = (cls1 < NCLS) ? W3[(j0 + 8 + 2 * lc) * NCLS + cls1] / 21.f : 0.f;
            float f31 = (cls1 < NCLS) ? W3[(j0 + 9 + 2 * lc) * NCLS + cls1] / 21.f : 0.f;
            __half2 h0 = __floats2half2_rn(f00, f01);
            __half2 h1 = __floats2half2_rn(f10, f11);
            __half2 h2v = __floats2half2_rn(f20, f21);
            __half2 h3 = __floats2half2_rn(f30, f31);
            a3w[mt][0] = *(unsigned*)&h0;
            a3w[mt][1] = *(unsigned*)&h1;
            a3w[mt][2] = *(unsigned*)&h2v;
            a3w[mt][3] = *(unsigned*)&h3;
        }
    }

    for (int tile = blockIdx.x; tile < NTILES; tile += GRID) {
        const int gbase = tile * 8;

        // ---- phase 1: layer 1 + mix + BN + ReLU + mix2 -> H (warp=graph) --
        {
            const float2 w1a = ((const float2*)(smf + SB_C / 4))[lane];
            const float2 w1b = ((const float2*)(smf + SB_C / 4 + 64))[lane];
            const float2 w1c = ((const float2*)(smf + SB_C / 4 + 128))[lane];
            const __half2 s1h = ((const __half2*)(smc + SB_S1))[lane];
            const __half2 t1h = ((const __half2*)(smc + SB_T1))[lane];
            const __half2 h05 = __float2half2_rn(0.5f);
            const __half2 hR2 = __float2half2_rn(R2C);
            const __half2 hz  = __float2half2_rn(0.f);
            const float* xg = x + (size_t)(gbase + wid) * 63;
            const float xv0 = xg[lane];
            const float xv1 = (lane < 31) ? xg[32 + lane] : 0.f;
            const int rb = 24 * wid;
            const int c4 = lane >> 2;
            const int lo = (lane & 3) * 4;

            __half2 z02, h02;
            {
                float xa = __shfl_sync(0xffffffffu, xv0, 0);
                float xb = __shfl_sync(0xffffffffu, xv0, 1);
                float xc = __shfl_sync(0xffffffffu, xv0, 2);
                float zx = fmaf(xa, w1a.x, fmaf(xb, w1b.x, xc * w1c.x));
                float zy = fmaf(xa, w1a.y, fmaf(xb, w1b.y, xc * w1c.y));
                z02 = __floats2half2_rn(zx, zy);
                h02 = __hmax2(__hfma2(z02, s1h, t1h), hz);
                *(__half2*)(smc + SB_H + rb * 128 + ((c4 ^ (rb & 7)) << 4) + lo)
                    = h02;
            }
            #pragma unroll
            for (int f = 0; f < 5; ++f) {
                __half2 zp2 = z02, hp2 = h02;
                #pragma unroll
                for (int i = 0; i < 4; ++i) {
                    const int n = 1 + 4 * f + i;
                    const __half2 cph = (i == 0) ? hR2 : h05;
                    const int i0 = 3 * n;
                    float xa = (i0 < 32) ? __shfl_sync(0xffffffffu, xv0, i0)
                                         : __shfl_sync(0xffffffffu, xv1, i0 - 32);
                    float xb = (i0 + 1 < 32) ? __shfl_sync(0xffffffffu, xv0, i0 + 1)
                                             : __shfl_sync(0xffffffffu, xv1, i0 - 31);
                    float xc = (i0 + 2 < 32) ? __shfl_sync(0xffffffffu, xv0, i0 + 2)
                                             : __shfl_sync(0xffffffffu, xv1, i0 - 30);
                    float zx = fmaf(xa, w1a.x, fmaf(xb, w1b.x, xc * w1c.x));
                    float zy = fmaf(xa, w1a.y, fmaf(xb, w1b.y, xc * w1c.y));
                    __half2 zn2 = __floats2half2_rn(zx, zy);
                    __half2 m12 = __hfma2(zn2, h05, __hmul2(zp2, cph));
                    __half2 hn2 = __hmax2(__hfma2(m12, s1h, t1h), hz);
                    __half2 m22 = __hfma2(hn2, h05, __hmul2(hp2, cph));
                    const int row = rb + n;
                    *(__half2*)(smc + SB_H + row * 128
                                + ((c4 ^ (row & 7)) << 4) + lo) = m22;
                    zp2 = zn2; hp2 = hn2;
                }
            }
        }
        __syncthreads();                              // BAR1: H ready

        // ---- phase 2: MMA (M=32, 12 nt) + MMA pooling ---------------------
        {
            float vC[2][4];
            #pragma unroll
            for (int mt = 0; mt < 2; ++mt)
                #pragma unroll
                for (int q = 0; q < 4; ++q) vC[mt][q] = 0.f;

            #pragma unroll
            for (int nt = 0; nt < 12; ++nt) {
                float acc[8] = {0.f,0.f,0.f,0.f,0.f,0.f,0.f,0.f};
                unsigned b[8];
                ldsm4(b[0], b[1], b[2], b[3], bB[0] + nt * 1024);
                ldsm4(b[4], b[5], b[6], b[7], bB[1] + nt * 1024);
                #pragma unroll
                for (int kk = 0; kk < 4; ++kk) {
                    mma16816(acc,     ah[kk][0], b[2 * kk], b[2 * kk + 1]);
                    mma16816(acc + 4, ah[kk][1], b[2 * kk], b[2 * kk + 1]);
                }
                unsigned bp;
                ldsm1(bp, bpAddr + nt * 128);
                #pragma unroll
                for (int mt = 0; mt < 2; ++mt) {
                    unsigned pa0 = relupack2(acc[4 * mt], acc[4 * mt + 1],
                                             t2h[2 * mt]);
                    unsigned pa1 = relupack2(acc[4 * mt + 2], acc[4 * mt + 3],
                                             t2h[2 * mt + 1]);
                    mma16808(vC[mt], pa0, pa1, bp);
                }
            }
            // store v as fp16 [g][j] (threads with lc<2 hold the 4 graphs)
            if (lc < 2) {
                #pragma unroll
                for (int mt = 0; mt < 2; ++mt) {
                    const int j = 32 * jq + 16 * mt + lr;
                    const int g0 = 4 * half + 2 * lc;
                    *(__half*)(smc + SB_VT + g0 * 256 + j * 2)
                        = __float2half(vC[mt][0]);
                    *(__half*)(smc + SB_VT + (g0 + 1) * 256 + j * 2)
                        = __float2half(vC[mt][1]);
                    *(__half*)(smc + SB_VT + g0 * 256 + (j + 8) * 2)
                        = __float2half(vC[mt][2]);
                    *(__half*)(smc + SB_VT + (g0 + 1) * 256 + (j + 8) * 2)
                        = __float2half(vC[mt][3]);
                }
            }
        }
        __syncthreads();                              // BAR2: VT ready

        // ---- phase 4: layer 3 via MMA (k-slice = 16 j per warp) -----------
        {
            const int j0 = 16 * wid;
            unsigned bv0 = *(unsigned*)(smc + SB_VT + lr * 256 + (j0 + 2 * lc) * 2);
            unsigned bv1 = *(unsigned*)(smc + SB_VT + lr * 256 + (j0 + 8 + 2 * lc) * 2);
            float yc[8] = {0.f,0.f,0.f,0.f,0.f,0.f,0.f,0.f};
            mma16816(yc,     a3w[0], bv0, bv1);
            mma16816(yc + 4, a3w[1], bv0, bv1);
            float* py = smf + SB_PY / 4 + wid * 256;
            #pragma unroll
            for (int mt = 0; mt < 2; ++mt) {
                py[(2 * lc)     * 32 + 16 * mt + lr]     = yc[4 * mt];
                py[(2 * lc + 1) * 32 + 16 * mt + lr]     = yc[4 * mt + 1];
                py[(2 * lc)     * 32 + 16 * mt + lr + 8] = yc[4 * mt + 2];
                py[(2 * lc + 1) * 32 + 16 * mt + lr + 8] = yc[4 * mt + 3];
            }
        }
        __syncthreads();                              // BAR3: PY ready

        // ---- phase 5: combine + log_softmax (warp = graph) ----------------
        {
            float yy = 0.f;
            #pragma unroll
            for (int w = 0; w < 8; ++w)
                yy += smf[SB_PY / 4 + w * 256 + wid * 32 + lane];
            float logit = (lane < NCLS) ? yy + smf[SB_B3 / 4 + lane] : -1e30f;
            float mx = logit;
            #pragma unroll
            for (int o = 16; o; o >>= 1)
                mx = fmaxf(mx, __shfl_xor_sync(0xffffffffu, mx, o));
            float e = (lane < NCLS) ? __expf(logit - mx) : 0.f;
            float s = e;
            #pragma unroll
            for (int o = 16; o; o >>= 1)
                s += __shfl_xor_sync(0xffffffffu, s, o);
            if (lane < NCLS)
                out[(size_t)(gbase + wid) * NCLS + lane]
                    = logit - mx - __logf(s);
        }
        // H/VT/PY cross-tile hazards ordered by the BAR1..BAR3 chain
    }
}

extern "C" void kernel_launch(void* const* d_in, const int* in_sizes, int n_in,
                              void* d_out, int out_size) {
    const float* x   = (const float*)d_in[0];
    const float* W1  = (const float*)d_in[1];
    const float* b1  = (const float*)d_in[2];
    const float* g1  = (const float*)d_in[3];
    const float* be1 = (const float*)d_in[4];
    const float* m1  = (const float*)d_in[5];
    const float* v1  = (const float*)d_in[6];
    const float* W2  = (const float*)d_in[7];
    const float* b2  = (const float*)d_in[8];
    const float* g2  = (const float*)d_in[9];
    const float* be2 = (const float*)d_in[10];
    const float* m2  = (const float*)d_in[11];
    const float* v2  = (const float*)d_in[12];
    const float* W3  = (const float*)d_in[13];
    const float* b3  = (const float*)d_in[14];

    cudaFuncSetAttribute(gcn_r11_kernel,
                         cudaFuncAttributeMaxDynamicSharedMemorySize, SB_TOT);
    gcn_r11_kernel<<<GRID, 256, SB_TOT>>>(
        x, W1, b1, g1, be1, m1, v1,
        W2, b2, g2, be2, m2, v2, W3, b3, (float*)d_out);
}

// round 12
// speedup vs baseline: 1.3167x; 1.0438x over previous
#include <cuda_runtime.h>
#include <cuda_fp16.h>
#include <math.h>

// ---------------------------------------------------------------------------
// Fused 3-layer GCN, fixed 21-node hand skeleton, 50000 graphs.
// R12 = R11 with layer-3 fused into phase 2:
//   * pooling C-fragment transposed in-warp via movmatrix.m8n8.trans.b16 ->
//     directly a B-fragment of the layer-3 m16n8k16 MMA (k=j, n=graph).
//     No VT smem round-trip, barriers 3 -> 2, PY partials 8 -> 4.
//   * W3^T A-fragments pre-staged in fragment order (LDS.128 per tile).
//   * phase-1 x distribution via smem broadcast instead of 63 SHFL.
// ---------------------------------------------------------------------------

#define NODES   21
#define NCLS    29
#define NTILES  6250          // 50000 / 8
#define GRID    444           // 148 SM x 3 CTA
#define R2C     0.70710678118654752440f
#define WROOT   4.535533905932737f

// ---- smem byte offsets ----------------------------------------------------
#define SB_H    0             // h1mix fp16 [192 rows][128B] swizzled  24576
#define SB_A    24576         // W2'*s2 fp16 [128 j][128B] swizzled    16384
#define SB_BP   40960         // pool B [12 nt][8 n][8 k] fp16         1536
#define SB_W3F  42496         // W3^T/21 frag order [4 jq][2 ks][2 mt][32][16B]
#define SB_PY   50688         // partial y [4 jq][2 half][4 gl][32] f32 4096
#define SB_X    54784         // x staged [8 w][21][4] f32             2688
#define SB_T2   57472         // 128 f32
#define SB_B3   57984         // 32 f32
#define SB_C    58112         // W1 [3][64] f32                        768
#define SB_S1   58880         // s1 half2 [32]                         128
#define SB_T1   59008         // t1 half2 [32]                         128
#define SB_TOT  59136         // x3 CTA = 177,408

// ---- PTX helpers ----------------------------------------------------------
__device__ __forceinline__ unsigned smem_u32(const void* p) {
    unsigned a;
    asm("{ .reg .u64 t; cvta.to.shared.u64 t, %1; cvt.u32.u64 %0, t; }"
        : "=r"(a) : "l"(p));
    return a;
}
__device__ __forceinline__ void ldsm4(unsigned& r0, unsigned& r1,
                                      unsigned& r2, unsigned& r3, unsigned a) {
    asm volatile("ldmatrix.sync.aligned.m8n8.x4.shared.b16 {%0,%1,%2,%3}, [%4];"
                 : "=r"(r0), "=r"(r1), "=r"(r2), "=r"(r3) : "r"(a));
}
__device__ __forceinline__ void ldsm1(unsigned& r0, unsigned a) {
    asm volatile("ldmatrix.sync.aligned.m8n8.x1.shared.b16 {%0}, [%1];"
                 : "=r"(r0) : "r"(a));
}
__device__ __forceinline__ unsigned movm(unsigned a) {
    unsigned d;
    asm volatile("movmatrix.sync.aligned.m8n8.trans.b16 %0, %1;"
                 : "=r"(d) : "r"(a));
    return d;
}
__device__ __forceinline__ void mma16816(float* c, const unsigned* a,
                                         unsigned b0, unsigned b1) {
    asm volatile(
        "mma.sync.aligned.m16n8k16.row.col.f32.f16.f16.f32 "
        "{%0,%1,%2,%3}, {%4,%5,%6,%7}, {%8,%9}, {%0,%1,%2,%3};"
        : "+f"(c[0]), "+f"(c[1]), "+f"(c[2]), "+f"(c[3])
        : "r"(a[0]), "r"(a[1]), "r"(a[2]), "r"(a[3]), "r"(b0), "r"(b1));
}
__device__ __forceinline__ void mma16808(float* c, unsigned a0, unsigned a1,
                                         unsigned b0) {
    asm volatile(
        "mma.sync.aligned.m16n8k8.row.col.f32.f16.f16.f32 "
        "{%0,%1,%2,%3}, {%4,%5}, {%6}, {%0,%1,%2,%3};"
        : "+f"(c[0]), "+f"(c[1]), "+f"(c[2]), "+f"(c[3])
        : "r"(a0), "r"(a1), "r"(b0));
}
__device__ __forceinline__ unsigned relupack2(float a, float b, __half2 t) {
    __half2 h = __floats2half2_rn(a, b);
    h = __hmax2(__hadd2(h, t), __float2half2_rn(0.f));
    return *(unsigned*)&h;
}
__device__ __forceinline__ float wraw(int l) {      // raw pooled node weight
    if (l == 0)  return WROOT;
    if (l >= 21) return 0.f;
    return ((l & 3) == 0) ? 0.5f : 1.0f;
}

// ---------------------------------------------------------------------------
__global__ void __launch_bounds__(256, 3)
gcn_r12_kernel(const float* __restrict__ x,
               const float* __restrict__ W1, const float* __restrict__ b1,
               const float* __restrict__ g1, const float* __restrict__ be1,
               const float* __restrict__ m1, const float* __restrict__ v1,
               const float* __restrict__ W2, const float* __restrict__ b2,
               const float* __restrict__ g2, const float* __restrict__ be2,
               const float* __restrict__ m2, const float* __restrict__ v2,
               const float* __restrict__ W3, const float* __restrict__ b3,
               float* __restrict__ out) {
    extern __shared__ char smc[];
    float* smf = (float*)smc;
    const unsigned sb = smem_u32(smc);
    const int tid  = threadIdx.x;
    const int lane = tid & 31;
    const int wid  = tid >> 5;          // 0..7
    const int jq   = wid & 3;           // j-strip of 32
    const int half = wid >> 2;          // 0: graphs 0-3, 1: graphs 4-7
    const int lr   = lane >> 2;         // fragment row
    const int lc   = lane & 3;          // fragment col-pair

    // ---------------- staging (once per CTA) -------------------------------
    for (int i = tid; i < 8192; i += 256) {          // A = W2^T*diag(s2), swz
        int j = i & 127, k = i >> 7;
        float s = g2[j] * rsqrtf(v2[j] + 1e-5f);
        int off = SB_A + j * 128 + (((k >> 3) ^ (j & 7)) << 4) + (k & 7) * 2;
        *(__half*)(smc + off) = __float2half(W2[k * 128 + j] * s);
    }
    for (int i = tid; i < 768; i += 256) {           // pool B [nt][n][k]
        int nt = i >> 6, n = (i >> 3) & 7, k = i & 7;
        int col = 8 * nt + k;
        int gl = col / 24, ln = col % 24;
        float v_ = (n == gl) ? wraw(ln) : 0.f;
        *(__half*)(smc + SB_BP + nt * 128 + n * 16 + k * 2) = __float2half(v_);
    }
    // W3^T/21 in A-fragment order: [jq][ks][mt][lane][q] half2
    for (int i = tid; i < 4096; i += 256) {
        int q   = i & 3;
        int ln  = (i >> 2) & 31;
        int mt  = (i >> 7) & 1;
        int ks  = (i >> 8) & 1;
        int jq_ = (i >> 9) & 3;
        int lr_ = ln >> 2, lc_ = ln & 3;
        int cls = 16 * mt + lr_ + 8 * (q & 1);
        int jj  = 32 * jq_ + 16 * ks + 2 * lc_ + 8 * (q >> 1);
        float f0 = (cls < NCLS) ? W3[jj * NCLS + cls] / 21.f : 0.f;
        float f1 = (cls < NCLS) ? W3[(jj + 1) * NCLS + cls] / 21.f : 0.f;
        ((__half2*)(smc + SB_W3F))[i] = __floats2half2_rn(f0, f1);
    }
    for (int i = tid; i < 768; i += 256) {           // zero H pad rows n=21..23
        int g = i / 96, rem = i % 96;
        int row = 24 * g + 21 + rem / 32;
        *(float*)(smc + SB_H + row * 128 + (rem % 32) * 4) = 0.f;
    }
    if (tid < 128) {
        float s = g2[tid] * rsqrtf(v2[tid] + 1e-5f);
        smf[SB_T2 / 4 + tid] = (b2[tid] - m2[tid]) * s + be2[tid];
    }
    if (tid < NCLS) smf[SB_B3 / 4 + tid] = b3[tid];
    for (int i = tid; i < 192; i += 256) smf[SB_C / 4 + i] = W1[i];
    if (tid < 32) {                                  // s1/t1 as half2 pairs
        int c2 = 2 * tid;
        float sa = g1[c2] * rsqrtf(v1[c2] + 1e-5f);
        float sbv = g1[c2 + 1] * rsqrtf(v1[c2 + 1] + 1e-5f);
        float ta = (b1[c2] - m1[c2]) * sa + be1[c2];
        float tb = (b1[c2 + 1] - m1[c2 + 1]) * sbv + be1[c2 + 1];
        ((__half2*)(smc + SB_S1))[tid] = __floats2half2_rn(sa, sbv);
        ((__half2*)(smc + SB_T1))[tid] = __floats2half2_rn(ta, tb);
    }
    __syncthreads();

    // ---- per-warp invariants ---------------------------------------------
    __half2 t2h[4];
    #pragma unroll
    for (int r = 0; r < 4; ++r)
        t2h[r] = __float2half2_rn(smf[SB_T2 / 4 + 32 * jq + lr + 8 * r]);
    unsigned bB[2];
    #pragma unroll
    for (int c = 0; c < 2; ++c)
        bB[c] = sb + SB_H + (96 * half + (lane & 7)) * 128
              + ((((lane >> 3) + 4 * c) ^ (lane & 7)) << 4);
    const unsigned bpAddr = sb + SB_BP + (lane & 7) * 16;
    float* const px = smf + SB_X / 4 + wid * 84;     // [21][4] per warp

    // main-GEMM A fragments (static W2 strip): load ONCE (32 regs)
    unsigned ah[4][2][4];
    #pragma unroll
    for (int kk = 0; kk < 4; ++kk)
        #pragma unroll
        for (int mt = 0; mt < 2; ++mt) {
            int row = 32 * jq + 16 * mt + (lane & 15);
            ldsm4(ah[kk][mt][0], ah[kk][mt][1], ah[kk][mt][2], ah[kk][mt][3],
                  sb + SB_A + row * 128
                  + ((((lane >> 4) + 2 * kk) ^ (row & 7)) << 4));
        }

    for (int tile = blockIdx.x; tile < NTILES; tile += GRID) {
        const int gbase = tile * 8;

        // ---- phase 1: layer 1 + mix + BN + ReLU + mix2 -> H (warp=graph) --
        {
            const float2 w1a = ((const float2*)(smf + SB_C / 4))[lane];
            const float2 w1b = ((const float2*)(smf + SB_C / 4 + 64))[lane];
            const float2 w1c = ((const float2*)(smf + SB_C / 4 + 128))[lane];
            const __half2 s1h = ((const __half2*)(smc + SB_S1))[lane];
            const __half2 t1h = ((const __half2*)(smc + SB_T1))[lane];
            const __half2 h05 = __float2half2_rn(0.5f);
            const __half2 hR2 = __float2half2_rn(R2C);
            const __half2 hz  = __float2half2_rn(0.f);
            const float* xg = x + (size_t)(gbase + wid) * 63;

            // stage x into per-warp padded buffer, then broadcast via LDS
            {
                float xa0 = xg[lane];
                px[(lane / 3) * 4 + lane % 3] = xa0;
                if (lane < 31) {
                    float xa1 = xg[32 + lane];
                    int p1 = 32 + lane;
                    px[(p1 / 3) * 4 + p1 % 3] = xa1;
                }
            }
            __syncwarp();

            const int rb = 24 * wid;
            const int c4 = lane >> 2;
            const int lo = (lane & 3) * 4;

            __half2 z02, h02;
            {
                float4 xq = *(const float4*)(px);
                float zx = fmaf(xq.x, w1a.x, fmaf(xq.y, w1b.x, xq.z * w1c.x));
                float zy = fmaf(xq.x, w1a.y, fmaf(xq.y, w1b.y, xq.z * w1c.y));
                z02 = __floats2half2_rn(zx, zy);
                h02 = __hmax2(__hfma2(z02, s1h, t1h), hz);
                *(__half2*)(smc + SB_H + rb * 128 + ((c4 ^ (rb & 7)) << 4) + lo)
                    = h02;
            }
            #pragma unroll
            for (int f = 0; f < 5; ++f) {
                __half2 zp2 = z02, hp2 = h02;
                #pragma unroll
                for (int i = 0; i < 4; ++i) {
                    const int n = 1 + 4 * f + i;
                    const __half2 cph = (i == 0) ? hR2 : h05;
                    float4 xq = *(const float4*)(px + 4 * n);
                    float zx = fmaf(xq.x, w1a.x, fmaf(xq.y, w1b.x, xq.z * w1c.x));
                    float zy = fmaf(xq.x, w1a.y, fmaf(xq.y, w1b.y, xq.z * w1c.y));
                    __half2 zn2 = __floats2half2_rn(zx, zy);
                    __half2 m12 = __hfma2(zn2, h05, __hmul2(zp2, cph));
                    __half2 hn2 = __hmax2(__hfma2(m12, s1h, t1h), hz);
                    __half2 m22 = __hfma2(hn2, h05, __hmul2(hp2, cph));
                    const int row = rb + n;
                    *(__half2*)(smc + SB_H + row * 128
                                + ((c4 ^ (row & 7)) << 4) + lo) = m22;
                    zp2 = zn2; hp2 = hn2;
                }
            }
        }
        __syncthreads();                              // BAR1: H ready

        // ---- phase 2: MMA + MMA pooling + fused MMA layer-3 ---------------
        {
            float vC[2][4];
            #pragma unroll
            for (int mt = 0; mt < 2; ++mt)
                #pragma unroll
                for (int q = 0; q < 4; ++q) vC[mt][q] = 0.f;

            #pragma unroll
            for (int nt = 0; nt < 12; ++nt) {
                float acc[8] = {0.f,0.f,0.f,0.f,0.f,0.f,0.f,0.f};
                unsigned b[8];
                ldsm4(b[0], b[1], b[2], b[3], bB[0] + nt * 1024);
                ldsm4(b[4], b[5], b[6], b[7], bB[1] + nt * 1024);
                #pragma unroll
                for (int kk = 0; kk < 4; ++kk) {
                    mma16816(acc,     ah[kk][0], b[2 * kk], b[2 * kk + 1]);
                    mma16816(acc + 4, ah[kk][1], b[2 * kk], b[2 * kk + 1]);
                }
                unsigned bp;
                ldsm1(bp, bpAddr + nt * 128);
                #pragma unroll
                for (int mt = 0; mt < 2; ++mt) {
                    unsigned pa0 = relupack2(acc[4 * mt], acc[4 * mt + 1],
                                             t2h[2 * mt]);
                    unsigned pa1 = relupack2(acc[4 * mt + 2], acc[4 * mt + 3],
                                             t2h[2 * mt + 1]);
                    mma16808(vC[mt], pa0, pa1, bp);
                }
            }

            // transpose vC (j x g) -> B-fragment (k=j, n=g) via movmatrix
            unsigned bT[2][2];
            #pragma unroll
            for (int mt = 0; mt < 2; ++mt) {
                __half2 p0 = __floats2half2_rn(vC[mt][0], vC[mt][1]);
                __half2 p1 = __floats2half2_rn(vC[mt][2], vC[mt][3]);
                bT[mt][0] = movm(*(unsigned*)&p0);    // j block lower 8
                bT[mt][1] = movm(*(unsigned*)&p1);    // j block upper 8
            }
            // layer-3 MMA: k = own 32 j's, A = W3^T/21 fragments from smem
            float yc[8] = {0.f,0.f,0.f,0.f,0.f,0.f,0.f,0.f};
            #pragma unroll
            for (int ks = 0; ks < 2; ++ks) {
                uint4 aw0 = *(const uint4*)(smc + SB_W3F
                            + ((jq * 2 + ks) * 2 + 0) * 512 + lane * 16);
                mma16816(yc, (const unsigned*)&aw0, bT[ks][0], bT[ks][1]);
                uint4 aw1 = *(const uint4*)(smc + SB_W3F
                            + ((jq * 2 + ks) * 2 + 1) * 512 + lane * 16);
                mma16816(yc + 4, (const unsigned*)&aw1, bT[ks][0], bT[ks][1]);
            }
            // store partial y: [jq][half][gl][32 c]; valid g-slots at lc<2
            if (lc < 2) {
                float* py = smf + SB_PY / 4 + ((jq * 2 + half) * 4) * 32;
                #pragma unroll
                for (int mt = 0; mt < 2; ++mt) {
                    py[(2 * lc)     * 32 + 16 * mt + lr]     = yc[4 * mt];
                    py[(2 * lc + 1) * 32 + 16 * mt + lr]     = yc[4 * mt + 1];
                    py[(2 * lc)     * 32 + 16 * mt + lr + 8] = yc[4 * mt + 2];
                    py[(2 * lc + 1) * 32 + 16 * mt + lr + 8] = yc[4 * mt + 3];
                }
            }
        }
        __syncthreads();                              // BAR2: PY ready

        // ---- phase 5: combine + log_softmax (warp = graph) ----------------
        {
            const int base = (half * 4 + (wid & 3)) * 32;  // [half][gl] slot
            float yy = smf[SB_PY / 4 + (0 * 2 + half) * 128 + (wid & 3) * 32 + lane]
                     + smf[SB_PY / 4 + (1 * 2 + half) * 128 + (wid & 3) * 32 + lane]
                     + smf[SB_PY / 4 + (2 * 2 + half) * 128 + (wid & 3) * 32 + lane]
                     + smf[SB_PY / 4 + (3 * 2 + half) * 128 + (wid & 3) * 32 + lane];
            (void)base;
            float logit = (lane < NCLS) ? yy + smf[SB_B3 / 4 + lane] : -1e30f;
            float mx = logit;
            #pragma unroll
            for (int o = 16; o; o >>= 1)
                mx = fmaxf(mx, __shfl_xor_sync(0xffffffffu, mx, o));
            float e = (lane < NCLS) ? __expf(logit - mx) : 0.f;
            float s = e;
            #pragma unroll
            for (int o = 16; o; o >>= 1)
                s += __shfl_xor_sync(0xffffffffu, s, o);
            if (lane < NCLS)
                out[(size_t)(gbase + wid) * NCLS + lane]
                    = logit - mx - __logf(s);
        }
        // H WAR: next P1 after this BAR2+P5; P5 reads PY before next BAR1,
        // next P4 writes PY after next BAR1 -> ordered.
    }
}

extern "C" void kernel_launch(void* const* d_in, const int* in_sizes, int n_in,
                              void* d_out, int out_size) {
    const float* x   = (const float*)d_in[0];
    const float* W1  = (const float*)d_in[1];
    const float* b1  = (const float*)d_in[2];
    const float* g1  = (const float*)d_in[3];
    const float* be1 = (const float*)d_in[4];
    const float* m1  = (const float*)d_in[5];
    const float* v1  = (const float*)d_in[6];
    const float* W2  = (const float*)d_in[7];
    const float* b2  = (const float*)d_in[8];
    const float* g2  = (const float*)d_in[9];
    const float* be2 = (const float*)d_in[10];
    const float* m2  = (const float*)d_in[11];
    const float* v2  = (const float*)d_in[12];
    const float* W3  = (const float*)d_in[13];
    const float* b3  = (const float*)d_in[14];

    cudaFuncSetAttribute(gcn_r12_kernel,
                         cudaFuncAttributeMaxDynamicSharedMemorySize, SB_TOT);
    gcn_r12_kernel<<<GRID, 256, SB_TOT>>>(
        x, W1, b1, g1, be1, m1, v1,
        W2, b2, g2, be2, m2, v2, W3, b3, (float*)d_out);
}